// round 4
// baseline (speedup 1.0000x reference)
#include <cuda_runtime.h>
#include <cstdint>

// ============================================================================
// Scratch (static __device__ globals — no dynamic allocation)
// ============================================================================
#define NDIM 4096
#define NELEM (NDIM * NDIM)

__device__ __align__(16) int8_t g_xq[NELEM];    // quantized x (int8), [m][k]
__device__ __align__(16) int8_t g_wq[NELEM];    // quantized W (int8), [o][k]
__device__ __align__(16) float  g_accum[NELEM]; // int-valued f32 accumulator [m][o]
__device__ float g_bq[NDIM];                    // requantized bias (int-valued f32)
__device__ float g_partial[2048];               // block absmax partials: [0,1024)=x, [1024,2048)=W
__device__ int   g_absbits[4];                  // [3] = accum absmax bits (zeroed in prep)
__device__ float g_scales[4];                   // in_scale, w_scale, b_scale, accum_scale

// ============================================================================
// Helpers
// ============================================================================
__device__ __forceinline__ uint32_t smem_u32(const void* p) {
    uint32_t a;
    asm("{ .reg .u64 t; cvta.to.shared.u64 t, %1; cvt.u32.u64 %0, t; }" : "=r"(a) : "l"(p));
    return a;
}
__device__ __forceinline__ float warp_max(float m) {
    #pragma unroll
    for (int o = 16; o > 0; o >>= 1) m = fmaxf(m, __shfl_xor_sync(0xFFFFFFFFu, m, o));
    return m;
}

// ============================================================================
// Launch 0: absmax of x and W -> per-block partials (no atomics, no reset)
// ============================================================================
__global__ void absmax_xw_kernel(const float* __restrict__ x, const float* __restrict__ W) {
    const int slot = blockIdx.y;                 // 0 = x, 1 = W
    const float4* v = (const float4*)(slot ? W : x);
    const int n4 = NELEM / 4;
    float m = 0.0f;
    for (int i = blockIdx.x * blockDim.x + threadIdx.x; i < n4; i += gridDim.x * blockDim.x) {
        float4 a = v[i];
        m = fmaxf(m, fmaxf(fmaxf(fabsf(a.x), fabsf(a.y)), fmaxf(fabsf(a.z), fabsf(a.w))));
    }
    m = warp_max(m);
    __shared__ float sm[8];
    if ((threadIdx.x & 31) == 0) sm[threadIdx.x >> 5] = m;
    __syncthreads();
    if (threadIdx.x == 0) {
        float r = sm[0];
        #pragma unroll
        for (int w = 1; w < 8; w++) r = fmaxf(r, sm[w]);
        g_partial[slot * 1024 + blockIdx.x] = r;
    }
}

// ============================================================================
// Launch 1: single-block prep — reduce partials + |b|, scales, bias requant,
//           zero the accum-max slot (graph replays deterministic).
// ============================================================================
__global__ void prep_kernel(const float* __restrict__ b) {
    const int tid = threadIdx.x;                 // 256 threads
    __shared__ float sred[3][8];

    float mx = 0.0f, mw = 0.0f, mb = 0.0f;
    for (int i = tid; i < 1024; i += 256) {
        mx = fmaxf(mx, g_partial[i]);
        mw = fmaxf(mw, g_partial[1024 + i]);
    }
    for (int i = tid; i < NDIM; i += 256) mb = fmaxf(mb, fabsf(b[i]));
    mx = warp_max(mx); mw = warp_max(mw); mb = warp_max(mb);
    if ((tid & 31) == 0) {
        sred[0][tid >> 5] = mx; sred[1][tid >> 5] = mw; sred[2][tid >> 5] = mb;
    }
    __syncthreads();
    if (tid == 0) {
        float ax = sred[0][0], aw = sred[1][0], ab = sred[2][0];
        #pragma unroll
        for (int w = 1; w < 8; w++) {
            ax = fmaxf(ax, sred[0][w]); aw = fmaxf(aw, sred[1][w]); ab = fmaxf(ab, sred[2][w]);
        }
        float in_s = 255.0f / (2.0f * ax);
        float w_s  = 255.0f / (2.0f * aw);
        float b_s  = 255.0f / (2.0f * ab);
        g_scales[0] = in_s; g_scales[1] = w_s; g_scales[2] = b_s; g_scales[3] = in_s * w_s;
        g_absbits[3] = 0;
    }
    __syncthreads();
    float b_s = g_scales[2], acc_s = g_scales[3];
    float f = acc_s / b_s;
    for (int i = tid; i < NDIM; i += 256) {
        float bb = fminf(fmaxf(rintf(b[i] * b_s), -128.0f), 127.0f);
        g_bq[i] = fminf(fmaxf(rintf(bb * f), -2147483648.0f), 2147483647.0f);
    }
}

// ============================================================================
// Launch 2: quantize x and W -> int8 (fused, blockIdx.y selects tensor)
// ============================================================================
__global__ void quant_xw_kernel(const float* __restrict__ x, const float* __restrict__ W) {
    const int which = blockIdx.y;                // 0 = x, 1 = W
    const float4* v = (const float4*)(which ? W : x);
    uint32_t* o = (uint32_t*)(which ? g_wq : g_xq);
    const float s = g_scales[which];
    const int n4 = NELEM / 4;
    for (int i = blockIdx.x * blockDim.x + threadIdx.x; i < n4; i += gridDim.x * blockDim.x) {
        float4 a = v[i];
        int ix = (int)fminf(fmaxf(rintf(a.x * s), -128.0f), 127.0f);
        int iy = (int)fminf(fmaxf(rintf(a.y * s), -128.0f), 127.0f);
        int iz = (int)fminf(fmaxf(rintf(a.z * s), -128.0f), 127.0f);
        int iw = (int)fminf(fmaxf(rintf(a.w * s), -128.0f), 127.0f);
        o[i] = (uint32_t)(ix & 0xFF) | ((uint32_t)(iy & 0xFF) << 8) |
               ((uint32_t)(iz & 0xFF) << 16) | ((uint32_t)(iw & 0xFF) << 24);
    }
}

// ============================================================================
// Launch 3: int8 GEMM (mma.sync m16n8k32.s8.s8.s32)
//   CTA tile 256x128, BK=64, warp tile 64x64 (8 warps, 4x2), 6-stage cp.async.
//   accum[m, o] = sum_k xq[m,k] * wq[o,k] + bq[o]
// ============================================================================
#define BM 256
#define BN 128
#define BK 64
#define STAGES 6
#define NKITER (NDIM / BK)                 // 64
#define STAGE_A (BM * BK)                  // 16384
#define STAGE_B (BN * BK)                  // 8192
#define STAGE_BYTES (STAGE_A + STAGE_B)    // 24576

__global__ void __launch_bounds__(256, 1) gemm_kernel() {
    extern __shared__ char smem[];
    __shared__ float sBias[BN];

    const int tid  = threadIdx.x;
    const int lane = tid & 31;
    const int warp = tid >> 5;
    const int wm = warp >> 1;      // 0..3 (M, 64 rows)
    const int wn = warp & 1;       // 0..1 (N, 64 cols)
    const int bm = blockIdx.y, bn = blockIdx.x;

    const int8_t* gA = g_xq + (size_t)bm * BM * NDIM;
    const int8_t* gB = g_wq + (size_t)bn * BN * NDIM;

    if (tid < BN) sBias[tid] = g_bq[bn * BN + tid];

    const uint32_t smem0 = smem_u32(smem);
    const int g = lane >> 3;   // ldmatrix 8-lane group
    const int r = lane & 7;

    // ---- precompute ldmatrix addresses (stage-0 relative) ----
    // swizzle: chunk' = chunk ^ ((row>>1)&3); 64B rows
    uint32_t aAddr[2][4], bAddr[2][4];
    #pragma unroll
    for (int kt = 0; kt < 2; kt++) {
        #pragma unroll
        for (int mt = 0; mt < 4; mt++) {
            int row = wm * 64 + mt * 16 + (g & 1) * 8 + r;
            int col = (kt * 2 + (g >> 1)) ^ ((row >> 1) & 3);
            aAddr[kt][mt] = smem0 + row * 64 + col * 16;
        }
        #pragma unroll
        for (int p = 0; p < 4; p++) {
            int row = wn * 64 + (2 * p + (g >> 1)) * 8 + r;
            int col = (kt * 2 + (g & 1)) ^ ((row >> 1) & 3);
            bAddr[kt][p] = smem0 + STAGE_A + row * 64 + col * 16;
        }
    }

    // ---- precompute cp.async offsets ----
    uint32_t wOffA[4], wOffB[2];
    uint32_t gOffA[4], gOffB[2];
    #pragma unroll
    for (int i = 0; i < 4; i++) {
        int c = tid + i * 256;             // 0..1023 (A chunks)
        int row = c >> 2, col = c & 3;
        wOffA[i] = row * 64 + ((col ^ ((row >> 1) & 3)) * 16);
        gOffA[i] = row * NDIM + col * 16;
    }
    #pragma unroll
    for (int i = 0; i < 2; i++) {
        int c = tid + i * 256;             // 0..511 (B chunks)
        int row = c >> 2, col = c & 3;
        wOffB[i] = STAGE_A + row * 64 + ((col ^ ((row >> 1) & 3)) * 16);
        gOffB[i] = row * NDIM + col * 16;
    }

    auto load_stage = [&](uint32_t sOff, int kc) {
        const int kb = kc * BK;
        #pragma unroll
        for (int i = 0; i < 4; i++)
            asm volatile("cp.async.cg.shared.global [%0], [%1], 16;"
                :: "r"(smem0 + sOff + wOffA[i]), "l"(gA + gOffA[i] + kb));
        #pragma unroll
        for (int i = 0; i < 2; i++)
            asm volatile("cp.async.cg.shared.global [%0], [%1], 16;"
                :: "r"(smem0 + sOff + wOffB[i]), "l"(gB + gOffB[i] + kb));
    };

    #pragma unroll
    for (int s = 0; s < STAGES - 1; s++) {
        load_stage(s * STAGE_BYTES, s);
        asm volatile("cp.async.commit_group;");
    }

    int acc[4][8][4];
    #pragma unroll
    for (int mt = 0; mt < 4; mt++)
        #pragma unroll
        for (int nt = 0; nt < 8; nt++)
            #pragma unroll
            for (int j = 0; j < 4; j++) acc[mt][nt][j] = 0;

    uint32_t sOffCur = 0, sOffPre = (STAGES - 1) * STAGE_BYTES;
    for (int kc = 0; kc < NKITER; kc++) {
        asm volatile("cp.async.wait_group %0;" :: "n"(STAGES - 2));
        __syncthreads();
        if (kc + STAGES - 1 < NKITER) load_stage(sOffPre, kc + STAGES - 1);
        asm volatile("cp.async.commit_group;");

        #pragma unroll
        for (int kt = 0; kt < 2; kt++) {
            uint32_t a[4][4];
            #pragma unroll
            for (int mt = 0; mt < 4; mt++)
                asm volatile("ldmatrix.sync.aligned.m8n8.x4.shared.b16 {%0,%1,%2,%3}, [%4];"
                    : "=r"(a[mt][0]), "=r"(a[mt][1]), "=r"(a[mt][2]), "=r"(a[mt][3])
                    : "r"(aAddr[kt][mt] + sOffCur));
            uint32_t b[8][2];
            #pragma unroll
            for (int p = 0; p < 4; p++) {
                uint32_t r0, r1, r2, r3;
                asm volatile("ldmatrix.sync.aligned.m8n8.x4.shared.b16 {%0,%1,%2,%3}, [%4];"
                    : "=r"(r0), "=r"(r1), "=r"(r2), "=r"(r3)
                    : "r"(bAddr[kt][p] + sOffCur));
                b[2 * p][0] = r0;     b[2 * p][1] = r1;
                b[2 * p + 1][0] = r2; b[2 * p + 1][1] = r3;
            }
            #pragma unroll
            for (int mt = 0; mt < 4; mt++)
                #pragma unroll
                for (int nt = 0; nt < 8; nt++) {
                    asm volatile(
                        "mma.sync.aligned.m16n8k32.row.col.s32.s8.s8.s32 "
                        "{%0,%1,%2,%3}, {%4,%5,%6,%7}, {%8,%9}, {%0,%1,%2,%3};"
                        : "+r"(acc[mt][nt][0]), "+r"(acc[mt][nt][1]),
                          "+r"(acc[mt][nt][2]), "+r"(acc[mt][nt][3])
                        : "r"(a[mt][0]), "r"(a[mt][1]), "r"(a[mt][2]), "r"(a[mt][3]),
                          "r"(b[nt][0]), "r"(b[nt][1]));
                }
        }
        sOffCur += STAGE_BYTES; if (sOffCur == STAGES * STAGE_BYTES) sOffCur = 0;
        sOffPre += STAGE_BYTES; if (sOffPre == STAGES * STAGE_BYTES) sOffPre = 0;
    }
    asm volatile("cp.async.wait_group 0;");

    // ---- Epilogue: add bias, store f32 accum, reduce max|accum| ----
    float lmax = 0.0f;
    #pragma unroll
    for (int mt = 0; mt < 4; mt++) {
        #pragma unroll
        for (int nt = 0; nt < 8; nt++) {
            int row0 = bm * BM + wm * 64 + mt * 16 + (lane >> 2);
            int lcol = wn * 64 + nt * 8 + (lane & 3) * 2;
            int col0 = bn * BN + lcol;
            float bq0 = sBias[lcol], bq1 = sBias[lcol + 1];
            float v0 = (float)acc[mt][nt][0] + bq0;
            float v1 = (float)acc[mt][nt][1] + bq1;
            float v2 = (float)acc[mt][nt][2] + bq0;
            float v3 = (float)acc[mt][nt][3] + bq1;
            *(float2*)(g_accum + (size_t)row0 * NDIM + col0)       = make_float2(v0, v1);
            *(float2*)(g_accum + (size_t)(row0 + 8) * NDIM + col0) = make_float2(v2, v3);
            lmax = fmaxf(lmax, fmaxf(fmaxf(fabsf(v0), fabsf(v1)), fmaxf(fabsf(v2), fabsf(v3))));
        }
    }
    lmax = warp_max(lmax);
    if (lane == 0) atomicMax(&g_absbits[3], __float_as_int(lmax));
}

// ============================================================================
// Launch 4: output requantize + dequantize
// ============================================================================
__global__ void requant_kernel(float* __restrict__ out, int n4) {
    float acc_s = g_scales[3];
    float amax = __int_as_float(g_absbits[3]);
    float out_sat = amax / acc_s;
    float out_scale = 255.0f / (2.0f * out_sat);
    float rq = out_scale / acc_s;
    const float4* in = (const float4*)g_accum;
    float4* o = (float4*)out;
    for (int i = blockIdx.x * blockDim.x + threadIdx.x; i < n4; i += gridDim.x * blockDim.x) {
        float4 a = in[i];
        float4 rv;
        rv.x = fminf(fmaxf(rintf(a.x * rq), -128.0f), 127.0f) / out_scale;
        rv.y = fminf(fmaxf(rintf(a.y * rq), -128.0f), 127.0f) / out_scale;
        rv.z = fminf(fmaxf(rintf(a.z * rq), -128.0f), 127.0f) / out_scale;
        rv.w = fminf(fmaxf(rintf(a.w * rq), -128.0f), 127.0f) / out_scale;
        o[i] = rv;
    }
}

// ============================================================================
// Launch
// ============================================================================
extern "C" void kernel_launch(void* const* d_in, const int* in_sizes, int n_in,
                              void* d_out, int out_size) {
    const float* x = (const float*)d_in[0];
    const float* W = (const float*)d_in[1];
    const float* b = (const float*)d_in[2];
    float* out = (float*)d_out;

    const int n4 = NELEM / 4;
    const int smem_bytes = STAGES * STAGE_BYTES;   // 147456

    cudaFuncSetAttribute(gemm_kernel, cudaFuncAttributeMaxDynamicSharedMemorySize, smem_bytes);

    absmax_xw_kernel<<<dim3(1024, 2), 256>>>(x, W);
    prep_kernel<<<1, 256>>>(b);
    quant_xw_kernel<<<dim3(1024, 2), 256>>>(x, W);
    gemm_kernel<<<dim3(NDIM / BN, NDIM / BM), 256, smem_bytes>>>();
    requant_kernel<<<1024, 256>>>(out, n4);
}

// round 5
// speedup vs baseline: 1.2509x; 1.2509x over previous
#include <cuda_runtime.h>
#include <cstdint>

// ============================================================================
// Scratch (static __device__ globals — no dynamic allocation)
// ============================================================================
#define NDIM 4096
#define NELEM (NDIM * NDIM)

__device__ __align__(16) int8_t g_xq[NELEM];    // quantized x (int8), [m][k]
__device__ __align__(16) int8_t g_wq[NELEM];    // quantized W (int8), [o][k]
__device__ __align__(16) float  g_accum[NELEM]; // int-valued f32 accumulator [m][o]
__device__ float g_bq[NDIM];                    // requantized bias (int-valued f32)
__device__ float g_partial[2048];               // block absmax partials: [0,1024)=x, [1024,2048)=W
__device__ int   g_absbits[4];                  // [3] = accum absmax bits (zeroed in prep)
__device__ float g_scales[4];                   // in_scale, w_scale, b_scale, accum_scale

// ============================================================================
// Helpers
// ============================================================================
__device__ __forceinline__ uint32_t smem_u32(const void* p) {
    uint32_t a;
    asm("{ .reg .u64 t; cvta.to.shared.u64 t, %1; cvt.u32.u64 %0, t; }" : "=r"(a) : "l"(p));
    return a;
}
__device__ __forceinline__ float warp_max(float m) {
    #pragma unroll
    for (int o = 16; o > 0; o >>= 1) m = fmaxf(m, __shfl_xor_sync(0xFFFFFFFFu, m, o));
    return m;
}

// ============================================================================
// Launch 0: absmax of x and W -> per-block partials (no atomics, no reset)
// ============================================================================
__global__ void absmax_xw_kernel(const float* __restrict__ x, const float* __restrict__ W) {
    const int slot = blockIdx.y;                 // 0 = x, 1 = W
    const float4* v = (const float4*)(slot ? W : x);
    const int n4 = NELEM / 4;
    float m = 0.0f;
    for (int i = blockIdx.x * blockDim.x + threadIdx.x; i < n4; i += gridDim.x * blockDim.x) {
        float4 a = v[i];
        m = fmaxf(m, fmaxf(fmaxf(fabsf(a.x), fabsf(a.y)), fmaxf(fabsf(a.z), fabsf(a.w))));
    }
    m = warp_max(m);
    __shared__ float sm[8];
    if ((threadIdx.x & 31) == 0) sm[threadIdx.x >> 5] = m;
    __syncthreads();
    if (threadIdx.x == 0) {
        float r = sm[0];
        #pragma unroll
        for (int w = 1; w < 8; w++) r = fmaxf(r, sm[w]);
        g_partial[slot * 1024 + blockIdx.x] = r;
    }
}

// ============================================================================
// Launch 1: single-block prep — reduce partials + |b|, scales, bias requant,
//           zero the accum-max slot (graph replays deterministic).
// ============================================================================
__global__ void prep_kernel(const float* __restrict__ b) {
    const int tid = threadIdx.x;                 // 256 threads
    __shared__ float sred[3][8];

    float mx = 0.0f, mw = 0.0f, mb = 0.0f;
    for (int i = tid; i < 1024; i += 256) {
        mx = fmaxf(mx, g_partial[i]);
        mw = fmaxf(mw, g_partial[1024 + i]);
    }
    for (int i = tid; i < NDIM; i += 256) mb = fmaxf(mb, fabsf(b[i]));
    mx = warp_max(mx); mw = warp_max(mw); mb = warp_max(mb);
    if ((tid & 31) == 0) {
        sred[0][tid >> 5] = mx; sred[1][tid >> 5] = mw; sred[2][tid >> 5] = mb;
    }
    __syncthreads();
    if (tid == 0) {
        float ax = sred[0][0], aw = sred[1][0], ab = sred[2][0];
        #pragma unroll
        for (int w = 1; w < 8; w++) {
            ax = fmaxf(ax, sred[0][w]); aw = fmaxf(aw, sred[1][w]); ab = fmaxf(ab, sred[2][w]);
        }
        float in_s = 255.0f / (2.0f * ax);
        float w_s  = 255.0f / (2.0f * aw);
        float b_s  = 255.0f / (2.0f * ab);
        g_scales[0] = in_s; g_scales[1] = w_s; g_scales[2] = b_s; g_scales[3] = in_s * w_s;
        g_absbits[3] = 0;
    }
    __syncthreads();
    float b_s = g_scales[2], acc_s = g_scales[3];
    float f = acc_s / b_s;
    for (int i = tid; i < NDIM; i += 256) {
        float bb = fminf(fmaxf(rintf(b[i] * b_s), -128.0f), 127.0f);
        g_bq[i] = fminf(fmaxf(rintf(bb * f), -2147483648.0f), 2147483647.0f);
    }
}

// ============================================================================
// Launch 2: quantize x and W -> int8 (fused, blockIdx.y selects tensor)
// ============================================================================
__global__ void quant_xw_kernel(const float* __restrict__ x, const float* __restrict__ W) {
    const int which = blockIdx.y;                // 0 = x, 1 = W
    const float4* v = (const float4*)(which ? W : x);
    uint32_t* o = (uint32_t*)(which ? g_wq : g_xq);
    const float s = g_scales[which];
    const int n4 = NELEM / 4;
    for (int i = blockIdx.x * blockDim.x + threadIdx.x; i < n4; i += gridDim.x * blockDim.x) {
        float4 a = v[i];
        int ix = (int)fminf(fmaxf(rintf(a.x * s), -128.0f), 127.0f);
        int iy = (int)fminf(fmaxf(rintf(a.y * s), -128.0f), 127.0f);
        int iz = (int)fminf(fmaxf(rintf(a.z * s), -128.0f), 127.0f);
        int iw = (int)fminf(fmaxf(rintf(a.w * s), -128.0f), 127.0f);
        o[i] = (uint32_t)(ix & 0xFF) | ((uint32_t)(iy & 0xFF) << 8) |
               ((uint32_t)(iz & 0xFF) << 16) | ((uint32_t)(iw & 0xFF) << 24);
    }
}

// ============================================================================
// Launch 3: int8 GEMM (mma.sync m16n8k32.s8.s8.s32)
//   CTA 128x128, BK=64, warp tile 64x32 (8 warps 2x4), 5-stage cp.async,
//   2 CTAs/SM (4 warps/SMSP). Hoisted ldmatrix/cp.async addressing.
// ============================================================================
#define BM 128
#define BN 128
#define BK 64
#define STAGES 5
#define NKITER (NDIM / BK)                 // 64
#define STAGE_A (BM * BK)                  // 8192
#define STAGE_BYTES (STAGE_A + BN * BK)    // 16384

__global__ void __launch_bounds__(256, 2) gemm_kernel() {
    extern __shared__ char smem[];
    __shared__ float sBias[BN];

    const int tid  = threadIdx.x;
    const int lane = tid & 31;
    const int warp = tid >> 5;
    const int wm = warp >> 2;      // 0..1 (M, 64 rows)
    const int wn = warp & 3;       // 0..3 (N, 32 cols)
    const int bm = blockIdx.y, bn = blockIdx.x;

    const int8_t* gA = g_xq + (size_t)bm * BM * NDIM;
    const int8_t* gB = g_wq + (size_t)bn * BN * NDIM;

    if (tid < BN) sBias[tid] = g_bq[bn * BN + tid];

    const uint32_t smem0 = smem_u32(smem);
    const int g = lane >> 3;   // ldmatrix 8-lane group
    const int r = lane & 7;

    // ---- hoisted ldmatrix addresses (stage-0 absolute; add sOffCur per use) ----
    // swizzle: chunk' = chunk ^ ((row>>1)&3); 64B rows
    uint32_t aAddr[2][4], bAddr[2][2];
    #pragma unroll
    for (int kt = 0; kt < 2; kt++) {
        #pragma unroll
        for (int mt = 0; mt < 4; mt++) {
            int row = wm * 64 + mt * 16 + (g & 1) * 8 + r;
            int col = (kt * 2 + (g >> 1)) ^ ((row >> 1) & 3);
            aAddr[kt][mt] = smem0 + row * 64 + col * 16;
        }
        #pragma unroll
        for (int p = 0; p < 2; p++) {
            int row = wn * 32 + (2 * p + (g >> 1)) * 8 + r;
            int col = (kt * 2 + (g & 1)) ^ ((row >> 1) & 3);
            bAddr[kt][p] = smem0 + STAGE_A + row * 64 + col * 16;
        }
    }

    // ---- hoisted cp.async offsets (A: 512 chunks, B: 512 chunks; 2/thread) ----
    uint32_t wOff[2];                 // smem write offset (same pattern for A half / B half)
    uint32_t gOff[2];                 // gmem row*NDIM + col*16
    #pragma unroll
    for (int i = 0; i < 2; i++) {
        int c = tid + i * 256;        // 0..511
        int row = c >> 2, col = c & 3;
        wOff[i] = row * 64 + ((col ^ ((row >> 1) & 3)) * 16);
        gOff[i] = row * NDIM + col * 16;
    }

    auto load_stage = [&](uint32_t sOff, int kc) {
        const int kb = kc * BK;
        #pragma unroll
        for (int i = 0; i < 2; i++)
            asm volatile("cp.async.cg.shared.global [%0], [%1], 16;"
                :: "r"(smem0 + sOff + wOff[i]), "l"(gA + gOff[i] + kb));
        #pragma unroll
        for (int i = 0; i < 2; i++)
            asm volatile("cp.async.cg.shared.global [%0], [%1], 16;"
                :: "r"(smem0 + sOff + STAGE_A + wOff[i]), "l"(gB + gOff[i] + kb));
    };

    #pragma unroll
    for (int s = 0; s < STAGES - 1; s++) {
        load_stage(s * STAGE_BYTES, s);
        asm volatile("cp.async.commit_group;");
    }

    int acc[4][4][4];
    #pragma unroll
    for (int mt = 0; mt < 4; mt++)
        #pragma unroll
        for (int nt = 0; nt < 4; nt++)
            #pragma unroll
            for (int j = 0; j < 4; j++) acc[mt][nt][j] = 0;

    uint32_t sOffCur = 0, sOffPre = (STAGES - 1) * STAGE_BYTES;
    for (int kc = 0; kc < NKITER; kc++) {
        asm volatile("cp.async.wait_group %0;" :: "n"(STAGES - 2));
        __syncthreads();
        if (kc + STAGES - 1 < NKITER) load_stage(sOffPre, kc + STAGES - 1);
        asm volatile("cp.async.commit_group;");

        #pragma unroll
        for (int kt = 0; kt < 2; kt++) {
            uint32_t a[4][4];
            #pragma unroll
            for (int mt = 0; mt < 4; mt++)
                asm volatile("ldmatrix.sync.aligned.m8n8.x4.shared.b16 {%0,%1,%2,%3}, [%4];"
                    : "=r"(a[mt][0]), "=r"(a[mt][1]), "=r"(a[mt][2]), "=r"(a[mt][3])
                    : "r"(aAddr[kt][mt] + sOffCur));
            uint32_t b[4][2];
            #pragma unroll
            for (int p = 0; p < 2; p++) {
                uint32_t r0, r1, r2, r3;
                asm volatile("ldmatrix.sync.aligned.m8n8.x4.shared.b16 {%0,%1,%2,%3}, [%4];"
                    : "=r"(r0), "=r"(r1), "=r"(r2), "=r"(r3)
                    : "r"(bAddr[kt][p] + sOffCur));
                b[2 * p][0] = r0;     b[2 * p][1] = r1;
                b[2 * p + 1][0] = r2; b[2 * p + 1][1] = r3;
            }
            #pragma unroll
            for (int mt = 0; mt < 4; mt++)
                #pragma unroll
                for (int nt = 0; nt < 4; nt++) {
                    asm volatile(
                        "mma.sync.aligned.m16n8k32.row.col.s32.s8.s8.s32 "
                        "{%0,%1,%2,%3}, {%4,%5,%6,%7}, {%8,%9}, {%0,%1,%2,%3};"
                        : "+r"(acc[mt][nt][0]), "+r"(acc[mt][nt][1]),
                          "+r"(acc[mt][nt][2]), "+r"(acc[mt][nt][3])
                        : "r"(a[mt][0]), "r"(a[mt][1]), "r"(a[mt][2]), "r"(a[mt][3]),
                          "r"(b[nt][0]), "r"(b[nt][1]));
                }
        }
        sOffCur += STAGE_BYTES; if (sOffCur == STAGES * STAGE_BYTES) sOffCur = 0;
        sOffPre += STAGE_BYTES; if (sOffPre == STAGES * STAGE_BYTES) sOffPre = 0;
    }
    asm volatile("cp.async.wait_group 0;");

    // ---- Epilogue: add bias, store f32 accum, reduce max|accum| ----
    float lmax = 0.0f;
    #pragma unroll
    for (int mt = 0; mt < 4; mt++) {
        #pragma unroll
        for (int nt = 0; nt < 4; nt++) {
            int row0 = bm * BM + wm * 64 + mt * 16 + (lane >> 2);
            int lcol = wn * 32 + nt * 8 + (lane & 3) * 2;
            int col0 = bn * BN + lcol;
            float bq0 = sBias[lcol], bq1 = sBias[lcol + 1];
            float v0 = (float)acc[mt][nt][0] + bq0;
            float v1 = (float)acc[mt][nt][1] + bq1;
            float v2 = (float)acc[mt][nt][2] + bq0;
            float v3 = (float)acc[mt][nt][3] + bq1;
            *(float2*)(g_accum + (size_t)row0 * NDIM + col0)       = make_float2(v0, v1);
            *(float2*)(g_accum + (size_t)(row0 + 8) * NDIM + col0) = make_float2(v2, v3);
            lmax = fmaxf(lmax, fmaxf(fmaxf(fabsf(v0), fabsf(v1)), fmaxf(fabsf(v2), fabsf(v3))));
        }
    }
    lmax = warp_max(lmax);
    if (lane == 0) atomicMax(&g_absbits[3], __float_as_int(lmax));
}

// ============================================================================
// Launch 4: output requantize + dequantize
// ============================================================================
__global__ void requant_kernel(float* __restrict__ out, int n4) {
    float acc_s = g_scales[3];
    float amax = __int_as_float(g_absbits[3]);
    float out_sat = amax / acc_s;
    float out_scale = 255.0f / (2.0f * out_sat);
    float rq = out_scale / acc_s;
    const float4* in = (const float4*)g_accum;
    float4* o = (float4*)out;
    for (int i = blockIdx.x * blockDim.x + threadIdx.x; i < n4; i += gridDim.x * blockDim.x) {
        float4 a = in[i];
        float4 rv;
        rv.x = fminf(fmaxf(rintf(a.x * rq), -128.0f), 127.0f) / out_scale;
        rv.y = fminf(fmaxf(rintf(a.y * rq), -128.0f), 127.0f) / out_scale;
        rv.z = fminf(fmaxf(rintf(a.z * rq), -128.0f), 127.0f) / out_scale;
        rv.w = fminf(fmaxf(rintf(a.w * rq), -128.0f), 127.0f) / out_scale;
        o[i] = rv;
    }
}

// ============================================================================
// Launch
// ============================================================================
extern "C" void kernel_launch(void* const* d_in, const int* in_sizes, int n_in,
                              void* d_out, int out_size) {
    const float* x = (const float*)d_in[0];
    const float* W = (const float*)d_in[1];
    const float* b = (const float*)d_in[2];
    float* out = (float*)d_out;

    const int n4 = NELEM / 4;
    const int smem_bytes = STAGES * STAGE_BYTES;   // 81920

    cudaFuncSetAttribute(gemm_kernel, cudaFuncAttributeMaxDynamicSharedMemorySize, smem_bytes);

    absmax_xw_kernel<<<dim3(1024, 2), 256>>>(x, W);
    prep_kernel<<<1, 256>>>(b);
    quant_xw_kernel<<<dim3(1024, 2), 256>>>(x, W);
    gemm_kernel<<<dim3(NDIM / BN, NDIM / BM), 256, smem_bytes>>>();
    requant_kernel<<<1024, 256>>>(out, n4);
}

// round 6
// speedup vs baseline: 1.2528x; 1.0015x over previous
#include <cuda_runtime.h>
#include <cstdint>

// ============================================================================
// Scratch (static __device__ globals — no dynamic allocation)
// ============================================================================
#define NDIM 4096
#define NELEM (NDIM * NDIM)

__device__ __align__(16) int8_t g_xq[NELEM];    // quantized x (int8), [m][k]
__device__ __align__(16) int8_t g_wq[NELEM];    // quantized W (int8), [o][k]
__device__ __align__(16) float  g_accum[NELEM]; // int-valued f32 accumulator [m][o]
__device__ float g_bq[NDIM];                    // requantized bias (int-valued f32)
__device__ float g_partial[2048];               // block absmax partials: [0,1024)=x, [1024,2048)=W
__device__ int   g_absbits[4];                  // [3] = accum absmax bits (zeroed in prep)
__device__ float g_scales[4];                   // in_scale, w_scale, b_scale, accum_scale

// ============================================================================
// Helpers
// ============================================================================
__device__ __forceinline__ uint32_t smem_u32(const void* p) {
    uint32_t a;
    asm("{ .reg .u64 t; cvta.to.shared.u64 t, %1; cvt.u32.u64 %0, t; }" : "=r"(a) : "l"(p));
    return a;
}
__device__ __forceinline__ float warp_max(float m) {
    #pragma unroll
    for (int o = 16; o > 0; o >>= 1) m = fmaxf(m, __shfl_xor_sync(0xFFFFFFFFu, m, o));
    return m;
}

// ============================================================================
// Launch 0: absmax of x and W -> per-block partials (no atomics, no reset)
// ============================================================================
__global__ void absmax_xw_kernel(const float* __restrict__ x, const float* __restrict__ W) {
    const int slot = blockIdx.y;                 // 0 = x, 1 = W
    const float4* v = (const float4*)(slot ? W : x);
    const int n4 = NELEM / 4;
    float m = 0.0f;
    for (int i = blockIdx.x * blockDim.x + threadIdx.x; i < n4; i += gridDim.x * blockDim.x) {
        float4 a = v[i];
        m = fmaxf(m, fmaxf(fmaxf(fabsf(a.x), fabsf(a.y)), fmaxf(fabsf(a.z), fabsf(a.w))));
    }
    m = warp_max(m);
    __shared__ float sm[8];
    if ((threadIdx.x & 31) == 0) sm[threadIdx.x >> 5] = m;
    __syncthreads();
    if (threadIdx.x == 0) {
        float r = sm[0];
        #pragma unroll
        for (int w = 1; w < 8; w++) r = fmaxf(r, sm[w]);
        g_partial[slot * 1024 + blockIdx.x] = r;
    }
}

// ============================================================================
// Launch 1: single-block prep — reduce partials + |b|, scales, bias requant,
//           zero the accum-max slot (graph replays deterministic).
// ============================================================================
__global__ void prep_kernel(const float* __restrict__ b) {
    const int tid = threadIdx.x;                 // 256 threads
    __shared__ float sred[3][8];

    float mx = 0.0f, mw = 0.0f, mb = 0.0f;
    for (int i = tid; i < 1024; i += 256) {
        mx = fmaxf(mx, g_partial[i]);
        mw = fmaxf(mw, g_partial[1024 + i]);
    }
    for (int i = tid; i < NDIM; i += 256) mb = fmaxf(mb, fabsf(b[i]));
    mx = warp_max(mx); mw = warp_max(mw); mb = warp_max(mb);
    if ((tid & 31) == 0) {
        sred[0][tid >> 5] = mx; sred[1][tid >> 5] = mw; sred[2][tid >> 5] = mb;
    }
    __syncthreads();
    if (tid == 0) {
        float ax = sred[0][0], aw = sred[1][0], ab = sred[2][0];
        #pragma unroll
        for (int w = 1; w < 8; w++) {
            ax = fmaxf(ax, sred[0][w]); aw = fmaxf(aw, sred[1][w]); ab = fmaxf(ab, sred[2][w]);
        }
        float in_s = 255.0f / (2.0f * ax);
        float w_s  = 255.0f / (2.0f * aw);
        float b_s  = 255.0f / (2.0f * ab);
        g_scales[0] = in_s; g_scales[1] = w_s; g_scales[2] = b_s; g_scales[3] = in_s * w_s;
        g_absbits[3] = 0;
    }
    __syncthreads();
    float b_s = g_scales[2], acc_s = g_scales[3];
    float f = acc_s / b_s;
    for (int i = tid; i < NDIM; i += 256) {
        float bb = fminf(fmaxf(rintf(b[i] * b_s), -128.0f), 127.0f);
        g_bq[i] = fminf(fmaxf(rintf(bb * f), -2147483648.0f), 2147483647.0f);
    }
}

// ============================================================================
// Launch 2: quantize x and W -> int8 (fused, blockIdx.y selects tensor)
// ============================================================================
__global__ void quant_xw_kernel(const float* __restrict__ x, const float* __restrict__ W) {
    const int which = blockIdx.y;                // 0 = x, 1 = W
    const float4* v = (const float4*)(which ? W : x);
    uint32_t* o = (uint32_t*)(which ? g_wq : g_xq);
    const float s = g_scales[which];
    const int n4 = NELEM / 4;
    for (int i = blockIdx.x * blockDim.x + threadIdx.x; i < n4; i += gridDim.x * blockDim.x) {
        float4 a = v[i];
        int ix = (int)fminf(fmaxf(rintf(a.x * s), -128.0f), 127.0f);
        int iy = (int)fminf(fmaxf(rintf(a.y * s), -128.0f), 127.0f);
        int iz = (int)fminf(fmaxf(rintf(a.z * s), -128.0f), 127.0f);
        int iw = (int)fminf(fmaxf(rintf(a.w * s), -128.0f), 127.0f);
        o[i] = (uint32_t)(ix & 0xFF) | ((uint32_t)(iy & 0xFF) << 8) |
               ((uint32_t)(iz & 0xFF) << 16) | ((uint32_t)(iw & 0xFF) << 24);
    }
}

// ============================================================================
// Launch 3: int8 GEMM (mma.sync m16n8k32.s8.s8.s32)
//   CTA 128x128, BK=128, warp tile 64x32 (8 warps 2x4), 3-stage cp.async,
//   2 CTAs/SM. 128B rows, swizzle chunk^=(row&7). 32 barriers total.
// ============================================================================
#define BM 128
#define BN 128
#define BK 128
#define STAGES 3
#define NKITER (NDIM / BK)                 // 32
#define STAGE_A (BM * BK)                  // 16384
#define STAGE_BYTES (STAGE_A + BN * BK)    // 32768

__global__ void __launch_bounds__(256, 2) gemm_kernel() {
    extern __shared__ char smem[];
    __shared__ float sBias[BN];

    const int tid  = threadIdx.x;
    const int lane = tid & 31;
    const int warp = tid >> 5;
    const int wm = warp >> 2;      // 0..1 (M, 64 rows)
    const int wn = warp & 3;       // 0..3 (N, 32 cols)
    const int bm = blockIdx.y, bn = blockIdx.x;

    const int8_t* gA = g_xq + (size_t)bm * BM * NDIM;
    const int8_t* gB = g_wq + (size_t)bn * BN * NDIM;

    if (tid < BN) sBias[tid] = g_bq[bn * BN + tid];

    const uint32_t smem0 = smem_u32(smem);
    const int g = lane >> 3;   // ldmatrix 8-lane group
    const int r = lane & 7;

    // ---- hoisted ldmatrix addresses at kt=0; per-kt via XOR (addr ^ (kt<<5)) ----
    // 128B rows; swizzle: chunk' = chunk ^ (row & 7)
    uint32_t aAddr0[4], bAddr0[2];
    #pragma unroll
    for (int mt = 0; mt < 4; mt++) {
        int row = wm * 64 + mt * 16 + (g & 1) * 8 + r;
        int col = (g >> 1) ^ (row & 7);            // kt=0 chunk
        aAddr0[mt] = smem0 + row * 128 + col * 16;
    }
    #pragma unroll
    for (int p = 0; p < 2; p++) {
        int row = wn * 32 + (2 * p + (g >> 1)) * 8 + r;
        int col = (g & 1) ^ (row & 7);             // kt=0 chunk
        bAddr0[p] = smem0 + STAGE_A + row * 128 + col * 16;
    }

    // ---- hoisted cp.async offsets: 1024 chunks per matrix per stage, 4/thread ----
    uint32_t wOff[4], gOff[4];
    #pragma unroll
    for (int i = 0; i < 4; i++) {
        int c = tid + i * 256;        // 0..1023
        int row = c >> 3, col = c & 7;
        wOff[i] = row * 128 + ((col ^ (row & 7)) * 16);
        gOff[i] = row * NDIM + col * 16;
    }

    auto load_stage = [&](uint32_t sOff, int kc) {
        const int kb = kc * BK;
        #pragma unroll
        for (int i = 0; i < 4; i++)
            asm volatile("cp.async.cg.shared.global [%0], [%1], 16;"
                :: "r"(smem0 + sOff + wOff[i]), "l"(gA + gOff[i] + kb));
        #pragma unroll
        for (int i = 0; i < 4; i++)
            asm volatile("cp.async.cg.shared.global [%0], [%1], 16;"
                :: "r"(smem0 + sOff + STAGE_A + wOff[i]), "l"(gB + gOff[i] + kb));
    };

    #pragma unroll
    for (int s = 0; s < STAGES - 1; s++) {
        load_stage(s * STAGE_BYTES, s);
        asm volatile("cp.async.commit_group;");
    }

    int acc[4][4][4];
    #pragma unroll
    for (int mt = 0; mt < 4; mt++)
        #pragma unroll
        for (int nt = 0; nt < 4; nt++)
            #pragma unroll
            for (int j = 0; j < 4; j++) acc[mt][nt][j] = 0;

    uint32_t sOffCur = 0, sOffPre = (STAGES - 1) * STAGE_BYTES;
    for (int kc = 0; kc < NKITER; kc++) {
        asm volatile("cp.async.wait_group %0;" :: "n"(STAGES - 2));
        __syncthreads();
        if (kc + STAGES - 1 < NKITER) load_stage(sOffPre, kc + STAGES - 1);
        asm volatile("cp.async.commit_group;");

        #pragma unroll
        for (int kt = 0; kt < 4; kt++) {
            const uint32_t ktx = sOffCur ^ (kt << 5);   // stage offset + kt chunk XOR
            uint32_t a[4][4];
            #pragma unroll
            for (int mt = 0; mt < 4; mt++)
                asm volatile("ldmatrix.sync.aligned.m8n8.x4.shared.b16 {%0,%1,%2,%3}, [%4];"
                    : "=r"(a[mt][0]), "=r"(a[mt][1]), "=r"(a[mt][2]), "=r"(a[mt][3])
                    : "r"((aAddr0[mt] + sOffCur) ^ (kt << 5)));
            uint32_t b[4][2];
            #pragma unroll
            for (int p = 0; p < 2; p++) {
                uint32_t r0, r1, r2, r3;
                asm volatile("ldmatrix.sync.aligned.m8n8.x4.shared.b16 {%0,%1,%2,%3}, [%4];"
                    : "=r"(r0), "=r"(r1), "=r"(r2), "=r"(r3)
                    : "r"((bAddr0[p] + sOffCur) ^ (kt << 5)));
                b[2 * p][0] = r0;     b[2 * p][1] = r1;
                b[2 * p + 1][0] = r2; b[2 * p + 1][1] = r3;
            }
            (void)ktx;
            #pragma unroll
            for (int mt = 0; mt < 4; mt++)
                #pragma unroll
                for (int nt = 0; nt < 4; nt++) {
                    asm volatile(
                        "mma.sync.aligned.m16n8k32.row.col.s32.s8.s8.s32 "
                        "{%0,%1,%2,%3}, {%4,%5,%6,%7}, {%8,%9}, {%0,%1,%2,%3};"
                        : "+r"(acc[mt][nt][0]), "+r"(acc[mt][nt][1]),
                          "+r"(acc[mt][nt][2]), "+r"(acc[mt][nt][3])
                        : "r"(a[mt][0]), "r"(a[mt][1]), "r"(a[mt][2]), "r"(a[mt][3]),
                          "r"(b[nt][0]), "r"(b[nt][1]));
                }
        }
        sOffCur += STAGE_BYTES; if (sOffCur == STAGES * STAGE_BYTES) sOffCur = 0;
        sOffPre += STAGE_BYTES; if (sOffPre == STAGES * STAGE_BYTES) sOffPre = 0;
    }
    asm volatile("cp.async.wait_group 0;");

    // ---- Epilogue: add bias, store f32 accum, reduce max|accum| ----
    float lmax = 0.0f;
    #pragma unroll
    for (int mt = 0; mt < 4; mt++) {
        #pragma unroll
        for (int nt = 0; nt < 4; nt++) {
            int row0 = bm * BM + wm * 64 + mt * 16 + (lane >> 2);
            int lcol = wn * 32 + nt * 8 + (lane & 3) * 2;
            int col0 = bn * BN + lcol;
            float bq0 = sBias[lcol], bq1 = sBias[lcol + 1];
            float v0 = (float)acc[mt][nt][0] + bq0;
            float v1 = (float)acc[mt][nt][1] + bq1;
            float v2 = (float)acc[mt][nt][2] + bq0;
            float v3 = (float)acc[mt][nt][3] + bq1;
            *(float2*)(g_accum + (size_t)row0 * NDIM + col0)       = make_float2(v0, v1);
            *(float2*)(g_accum + (size_t)(row0 + 8) * NDIM + col0) = make_float2(v2, v3);
            lmax = fmaxf(lmax, fmaxf(fmaxf(fabsf(v0), fabsf(v1)), fmaxf(fabsf(v2), fabsf(v3))));
        }
    }
    lmax = warp_max(lmax);
    if (lane == 0) atomicMax(&g_absbits[3], __float_as_int(lmax));
}

// ============================================================================
// Launch 4: output requantize + dequantize
// ============================================================================
__global__ void requant_kernel(float* __restrict__ out, int n4) {
    float acc_s = g_scales[3];
    float amax = __int_as_float(g_absbits[3]);
    float out_sat = amax / acc_s;
    float out_scale = 255.0f / (2.0f * out_sat);
    float rq = out_scale / acc_s;
    const float4* in = (const float4*)g_accum;
    float4* o = (float4*)out;
    for (int i = blockIdx.x * blockDim.x + threadIdx.x; i < n4; i += gridDim.x * blockDim.x) {
        float4 a = in[i];
        float4 rv;
        rv.x = fminf(fmaxf(rintf(a.x * rq), -128.0f), 127.0f) / out_scale;
        rv.y = fminf(fmaxf(rintf(a.y * rq), -128.0f), 127.0f) / out_scale;
        rv.z = fminf(fmaxf(rintf(a.z * rq), -128.0f), 127.0f) / out_scale;
        rv.w = fminf(fmaxf(rintf(a.w * rq), -128.0f), 127.0f) / out_scale;
        o[i] = rv;
    }
}

// ============================================================================
// Launch
// ============================================================================
extern "C" void kernel_launch(void* const* d_in, const int* in_sizes, int n_in,
                              void* d_out, int out_size) {
    const float* x = (const float*)d_in[0];
    const float* W = (const float*)d_in[1];
    const float* b = (const float*)d_in[2];
    float* out = (float*)d_out;

    const int n4 = NELEM / 4;
    const int smem_bytes = STAGES * STAGE_BYTES;   // 98304

    cudaFuncSetAttribute(gemm_kernel, cudaFuncAttributeMaxDynamicSharedMemorySize, smem_bytes);

    absmax_xw_kernel<<<dim3(1024, 2), 256>>>(x, W);
    prep_kernel<<<1, 256>>>(b);
    quant_xw_kernel<<<dim3(1024, 2), 256>>>(x, W);
    gemm_kernel<<<dim3(NDIM / BN, NDIM / BM), 256, smem_bytes>>>();
    requant_kernel<<<1024, 256>>>(out, n4);
}